// round 13
// baseline (speedup 1.0000x reference)
#include <cuda_runtime.h>
#include <cuda_fp16.h>
#include <stdint.h>
#include <math.h>
#include <float.h>

#define NTHREADS   256
#define T_REAL     200
#define MASK_VAL_F (-4294967296.0f)   // jnp.float32(-2**32+1) rounds to -2^32

// fp16 SMEM tiles, row stride 72 elements (144 B: 16B-aligned, conflict-free ldmatrix)
#define ROWB       144
#define WSTRIP     (16 * ROWB)             // 2304 B per 16-row block strip
#define NSTRIPS    13                      // ceil(200/16)

// ---- SMEM byte offsets ----
#define OFF_K     0                        // keys fp16, 13 block strips : 29952
#define OFF_WQ    (NSTRIPS * WSTRIP)       // Weff^T fp16 [64][72] : 9216
#define OFF_W2    (OFF_WQ + 9216)          // W2^T  fp16 [32][72]  : 4608
#define OFF_SC    (OFF_W2 + 4608)          // fp32 scalars
#define SMEM_TOTAL (OFF_SC + 1920)         // 45696 B

// ---------------- PTX helpers (baseline, no sm_103a-only features) ----------------
static __device__ __forceinline__ uint32_t smem_u32(const void* p) {
    uint32_t a;
    asm("{ .reg .u64 t; cvta.to.shared.u64 t, %1; cvt.u32.u64 %0, t; }" : "=r"(a) : "l"(p));
    return a;
}

#define LDMX4(r, addr) \
    asm volatile("ldmatrix.sync.aligned.m8n8.x4.shared.b16 {%0,%1,%2,%3}, [%4];" \
        : "=r"((r)[0]), "=r"((r)[1]), "=r"((r)[2]), "=r"((r)[3]) : "r"(addr))

#define MMA16816(d, a, b0, b1) \
    asm volatile("mma.sync.aligned.m16n8k16.row.col.f32.f16.f16.f32 " \
        "{%0,%1,%2,%3},{%4,%5,%6,%7},{%8,%9},{%0,%1,%2,%3};" \
        : "+f"((d)[0]), "+f"((d)[1]), "+f"((d)[2]), "+f"((d)[3]) \
        : "r"((a)[0]), "r"((a)[1]), "r"((a)[2]), "r"((a)[3]), "r"(b0), "r"(b1))

// pack (x0 -> low half, x1 -> high half) into one fp16x2 register
static __device__ __forceinline__ uint32_t h2pack(float x0, float x1) {
    uint32_t h;
    asm("cvt.rn.f16x2.f32 %0, %1, %2;" : "=r"(h) : "f"(x1), "f"(x0));
    return h;
}

__device__ __forceinline__ float warpRedMax(float v) {
    #pragma unroll
    for (int o = 16; o > 0; o >>= 1) v = fmaxf(v, __shfl_xor_sync(0xffffffffu, v, o));
    return v;
}
__device__ __forceinline__ float warpRedSum(float v) {
    #pragma unroll
    for (int o = 16; o > 0; o >>= 1) v += __shfl_xor_sync(0xffffffffu, v, o);
    return v;
}

extern "C" __global__ void __launch_bounds__(NTHREADS, 3)
asp_kernel(const float* __restrict__ query,
           const float* __restrict__ keys,
           const int*   __restrict__ klw,
           const float* __restrict__ W1,
           const float* __restrict__ b1,
           const float* __restrict__ W2,
           const float* __restrict__ b2,
           const float* __restrict__ W3,
           const float* __restrict__ b3,
           float* __restrict__ out)
{
    extern __shared__ char sbase[];
    const uint32_t sb = smem_u32(sbase);

    float* qS   = (float*)(sbase + OFF_SC);          // 64
    float* qWbS = qS   + 64;                         // 64
    float* b2S  = qWbS + 64;                         // 32
    float* W3S  = b2S  + 32;                         // 32
    float* wS   = W3S  + 32;                         // 256 (also qWb-partial scratch)
    float* redS = wS   + 256;                        // 32

    const int b    = blockIdx.x;
    const int tid  = threadIdx.x;
    const int lane = tid & 31;
    const int warp = tid >> 5;

    const float* qg = query + (size_t)b * 64;
    const float* kg = keys  + (size_t)b * T_REAL * 64;

    int len;
    {
        const bool is64 = ((klw[1] | klw[3] | klw[5] | klw[7] | klw[9] | klw[11]) == 0);
        len = is64 ? klw[2 * b] : klw[b];
    }
    const float b3v = b3[0];

    // ---- stage small operands ----
    if (tid < 64)       qS[tid]     = qg[tid];
    else if (tid < 96)  W3S[tid-64] = W3[tid-64];
    else if (tid < 128) b2S[tid-96] = b2[tid-96];
    __syncthreads();

    // ---- qWb partials: thread (g=tid>>6, j=tid&63) sums i in [16g,16g+16) ----
    {
        const int j = tid & 63, g = tid >> 6;
        float s = 0.f;
        #pragma unroll 4
        for (int i = 16 * g; i < 16 * g + 16; i++)
            s += qS[i] * (W1[i*64 + j] + W1[(128+i)*64 + j]);
        wS[tid] = s;
    }
    // ---- Weff^T fp16 (paired over i): WqT[j][i] ----
    for (int idx = tid; idx < 2048; idx += NTHREADS) {
        const int j = idx & 63, i0 = (idx >> 6) * 2;
        const float w0 = W1[(64+i0)*64 + j] - W1[(128+i0)*64 + j] + qS[i0]   * W1[(192+i0)*64 + j];
        const float w1 = W1[(65+i0)*64 + j] - W1[(129+i0)*64 + j] + qS[i0+1] * W1[(193+i0)*64 + j];
        *(uint32_t*)(sbase + OFF_WQ + j*ROWB + i0*2) = h2pack(w0, w1);
    }
    // ---- W2^T fp16: W2T[n][i] ----
    for (int idx = tid; idx < 1024; idx += NTHREADS) {
        const int n = idx & 31, i0 = (idx >> 5) * 2;
        *(uint32_t*)(sbase + OFF_W2 + n*ROWB + i0*2) =
            h2pack(W2[i0*32 + n], W2[(i0+1)*32 + n]);
    }
    __syncthreads();

    // ---- phase 3: qWb finalize + stage ALL key strips (round-robin warps) ----
    if (tid < 64)
        qWbS[tid] = b1[tid] + wS[tid] + wS[64+tid] + wS[128+tid] + wS[192+tid];
    #pragma unroll 1
    for (int s = warp; s < NSTRIPS; s += 8) {
        char* stp = sbase + OFF_K + s * WSTRIP;
        #pragma unroll
        for (int it = 0; it < 8; it++) {
            const int idx = it * 32 + lane;
            const int row = idx >> 4, q4 = idx & 15;
            const int t = s * 16 + row;
            float4 v = make_float4(0.f, 0.f, 0.f, 0.f);
            if (t < T_REAL) v = ((const float4*)kg)[t * 16 + q4];
            *(uint2*)(stp + row*ROWB + q4*8) =
                make_uint2(h2pack(v.x, v.y), h2pack(v.z, v.w));
        }
    }
    __syncthreads();

    // ---- ldmatrix lane addressing ----
    const uint32_t laneR16 = lane & 15;
    const uint32_t laneC   = (lane >> 4) << 3;
    const uint32_t bNt = (lane >> 4) & 1;
    const uint32_t bK  = ((lane >> 3) & 1) << 3;
    const uint32_t bR  = lane & 7;
    const uint32_t bBase = (uint32_t)(bNt * 8 + bR) * ROWB + bK * 2;

    // ---- paired 16-row blocks: warp w -> blocks (2w, 2w+1) ----
    const int blkA = warp * 2, blkB = warp * 2 + 1;
    const bool hasA = (blkA < NSTRIPS), hasB = (blkB < NSTRIPS);

    if (hasA) {
        const uint32_t kA = sb + OFF_K + blkA * WSTRIP;
        const uint32_t kB = sb + OFF_K + (hasB ? blkB : blkA) * WSTRIP;

        uint32_t a2A[4][4], a2B[4][4];

        // ---- layer 1 in nt-halves: C1[32 x 64] paired ----
        #pragma unroll
        for (int hf = 0; hf < 2; hf++) {
            float c1A[4][4], c1B[4][4];
            #pragma unroll
            for (int q = 0; q < 4; q++)
                #pragma unroll
                for (int x = 0; x < 4; x++) { c1A[q][x] = 0.f; c1B[q][x] = 0.f; }

            #pragma unroll
            for (int kk = 0; kk < 4; kk++) {
                const uint32_t aoff = laneR16 * ROWB + (kk*16 + laneC) * 2;
                uint32_t aA[4], aB[4];
                LDMX4(aA, kA + aoff);
                LDMX4(aB, kB + aoff);
                #pragma unroll
                for (int pp = 0; pp < 2; pp++) {
                    const int ntp = hf * 2 + pp;
                    const uint32_t boff = (uint32_t)(ntp * 16) * ROWB + kk * 32 + bBase;
                    uint32_t bH[4];
                    LDMX4(bH, sb + OFF_WQ + boff);
                    MMA16816(c1A[pp*2+0], aA, bH[0], bH[1]);
                    MMA16816(c1A[pp*2+1], aA, bH[2], bH[3]);
                    MMA16816(c1B[pp*2+0], aB, bH[0], bH[1]);
                    MMA16816(c1B[pp*2+1], aB, bH[2], bH[3]);
                }
            }
            // epilogue half: relu(+qWb) -> fp16 A2 frags
            #pragma unroll
            for (int q = 0; q < 4; q++) {
                const int nt = hf * 4 + q;
                const int n0 = nt*8 + 2*(lane & 3);
                const float q0 = qWbS[n0], q1 = qWbS[n0+1];
                const int kk2 = nt >> 1, s = (nt & 1) * 2;
                a2A[kk2][s+0] = h2pack(fmaxf(c1A[q][0] + q0, 0.f), fmaxf(c1A[q][1] + q1, 0.f));
                a2A[kk2][s+1] = h2pack(fmaxf(c1A[q][2] + q0, 0.f), fmaxf(c1A[q][3] + q1, 0.f));
                a2B[kk2][s+0] = h2pack(fmaxf(c1B[q][0] + q0, 0.f), fmaxf(c1B[q][1] + q1, 0.f));
                a2B[kk2][s+1] = h2pack(fmaxf(c1B[q][2] + q0, 0.f), fmaxf(c1B[q][3] + q1, 0.f));
            }
        }

        // ---- layer 2 in pp-halves, score folded immediately ----
        float pA0 = 0.f, pA1 = 0.f, pB0 = 0.f, pB1 = 0.f;
        #pragma unroll
        for (int pp = 0; pp < 2; pp++) {
            float c2A[2][4], c2B[2][4];
            #pragma unroll
            for (int q = 0; q < 2; q++)
                #pragma unroll
                for (int x = 0; x < 4; x++) { c2A[q][x] = 0.f; c2B[q][x] = 0.f; }

            #pragma unroll
            for (int kk = 0; kk < 4; kk++) {
                const uint32_t boff = (uint32_t)(pp * 16) * ROWB + kk * 32 + bBase;
                uint32_t bH[4];
                LDMX4(bH, sb + OFF_W2 + boff);
                MMA16816(c2A[0], a2A[kk], bH[0], bH[1]);
                MMA16816(c2A[1], a2A[kk], bH[2], bH[3]);
                MMA16816(c2B[0], a2B[kk], bH[0], bH[1]);
                MMA16816(c2B[1], a2B[kk], bH[2], bH[3]);
            }
            #pragma unroll
            for (int q = 0; q < 2; q++) {
                const int nt = pp*2 + q;
                const int n0 = nt*8 + 2*(lane & 3);
                const float w0 = W3S[n0], w1 = W3S[n0+1];
                const float bb0 = b2S[n0], bb1 = b2S[n0+1];
                pA0 += fmaxf(c2A[q][0] + bb0, 0.f) * w0 + fmaxf(c2A[q][1] + bb1, 0.f) * w1;
                pA1 += fmaxf(c2A[q][2] + bb0, 0.f) * w0 + fmaxf(c2A[q][3] + bb1, 0.f) * w1;
                pB0 += fmaxf(c2B[q][0] + bb0, 0.f) * w0 + fmaxf(c2B[q][1] + bb1, 0.f) * w1;
                pB1 += fmaxf(c2B[q][2] + bb0, 0.f) * w0 + fmaxf(c2B[q][3] + bb1, 0.f) * w1;
            }
        }
        // quad reduce + write scores
        pA0 += __shfl_xor_sync(0xffffffffu, pA0, 1);
        pA0 += __shfl_xor_sync(0xffffffffu, pA0, 2);
        pA1 += __shfl_xor_sync(0xffffffffu, pA1, 1);
        pA1 += __shfl_xor_sync(0xffffffffu, pA1, 2);
        pB0 += __shfl_xor_sync(0xffffffffu, pB0, 1);
        pB0 += __shfl_xor_sync(0xffffffffu, pB0, 2);
        pB1 += __shfl_xor_sync(0xffffffffu, pB1, 1);
        pB1 += __shfl_xor_sync(0xffffffffu, pB1, 2);
        if ((lane & 3) == 0) {
            const int r = lane >> 2;
            wS[blkA*16 + r]     = pA0 + b3v;
            wS[blkA*16 + r + 8] = pA1 + b3v;
            if (hasB) {
                wS[blkB*16 + r]     = pB0 + b3v;
                wS[blkB*16 + r + 8] = pB1 + b3v;
            }
        }
    }
    __syncthreads();

    // ---- mask + softmax over wS ----
    float sc;
    if (tid < T_REAL) sc = (tid < len) ? wS[tid] : MASK_VAL_F;
    else              sc = -FLT_MAX;

    float m = warpRedMax(sc);
    if ((tid & 31) == 0) redS[tid >> 5] = m;
    __syncthreads();
    float bm = redS[0];
    #pragma unroll
    for (int w = 1; w < 8; w++) bm = fmaxf(bm, redS[w]);
    __syncthreads();
    const float e = (tid < T_REAL) ? expf(sc - bm) : 0.f;
    float s1 = warpRedSum(e);
    if ((tid & 31) == 0) redS[tid >> 5] = s1;
    __syncthreads();
    float bs = 0.f;
    #pragma unroll
    for (int w = 0; w < 8; w++) bs += redS[w];
    wS[tid] = e * (1.0f / bs);
    __syncthreads();

    // ---- weighted sum from SMEM fp16 keys: out[e] = sum_t w_t * k16[t][e] ----
    // strip layout linearizes: addr = OFF_K + t*ROWB + e*2
    float* scr = (float*)(sbase + OFF_WQ);   // reuse as fp32 scratch (256 floats)
    {
        const int e_ = tid & 63;
        const int g  = tid >> 6;
        const char* kbase = sbase + OFF_K + e_ * 2;
        float acc0 = 0.f, acc1 = 0.f;
        #pragma unroll 4
        for (int t = g; t < 192; t += 8) {
            acc0 += wS[t]     * __half2float(*(const __half*)(kbase + t * ROWB));
            acc1 += wS[t + 4] * __half2float(*(const __half*)(kbase + (t + 4) * ROWB));
        }
        acc0 += wS[192 + g] * __half2float(*(const __half*)(kbase + (192 + g) * ROWB));
        acc1 += wS[196 + g] * __half2float(*(const __half*)(kbase + (196 + g) * ROWB));
        scr[g * 64 + e_] = acc0 + acc1;
    }
    __syncthreads();
    if (tid < 64)
        out[(size_t)b * 64 + tid] =
            scr[tid] + scr[64 + tid] + scr[128 + tid] + scr[192 + tid];
}

extern "C" void kernel_launch(void* const* d_in, const int* in_sizes, int n_in,
                              void* d_out, int out_size) {
    const float* query = (const float*)d_in[0];
    const float* keys  = (const float*)d_in[1];
    const int*   klen  = (const int*)  d_in[2];
    const float* W1    = (const float*)d_in[3];
    const float* b1    = (const float*)d_in[4];
    const float* W2    = (const float*)d_in[5];
    const float* b2    = (const float*)d_in[6];
    const float* W3    = (const float*)d_in[7];
    const float* b3    = (const float*)d_in[8];
    float* out = (float*)d_out;

    const int B = in_sizes[0] / 64;

    cudaFuncSetAttribute(asp_kernel,
                         cudaFuncAttributeMaxDynamicSharedMemorySize,
                         SMEM_TOTAL);

    asp_kernel<<<B, NTHREADS, SMEM_TOTAL>>>(query, keys, klen,
                                            W1, b1, W2, b2, W3, b3, out);
}

// round 14
// speedup vs baseline: 1.2655x; 1.2655x over previous
#include <cuda_runtime.h>
#include <cuda_fp16.h>
#include <stdint.h>
#include <math.h>
#include <float.h>

#define NTHREADS   256
#define T_REAL     200
#define MASK_VAL_F (-4294967296.0f)   // jnp.float32(-2**32+1) rounds to -2^32

// fp16 SMEM tiles, row stride 72 elements (144 B: 16B-aligned, conflict-free ldmatrix)
#define ROWB       144
#define WSTRIP     (16 * ROWB)             // 2304 B per 16-row block strip
#define NSTRIPS    13                      // ceil(200/16)

// ---- SMEM byte offsets ----
#define OFF_K     0                        // keys fp16, 13 block strips : 29952
#define OFF_WQ    (NSTRIPS * WSTRIP)       // Weff^T fp16 [64][72] : 9216
#define OFF_W2    (OFF_WQ + 9216)          // W2^T  fp16 [32][72]  : 4608
#define OFF_SC    (OFF_W2 + 4608)          // fp32 scalars
#define SMEM_TOTAL (OFF_SC + 1920)         // 45696 B -> 4 CTAs/SM

// ---------------- PTX helpers (baseline, no sm_103a-only features) ----------------
static __device__ __forceinline__ uint32_t smem_u32(const void* p) {
    uint32_t a;
    asm("{ .reg .u64 t; cvta.to.shared.u64 t, %1; cvt.u32.u64 %0, t; }" : "=r"(a) : "l"(p));
    return a;
}

#define LDMX4(r, addr) \
    asm volatile("ldmatrix.sync.aligned.m8n8.x4.shared.b16 {%0,%1,%2,%3}, [%4];" \
        : "=r"((r)[0]), "=r"((r)[1]), "=r"((r)[2]), "=r"((r)[3]) : "r"(addr))

#define MMA16816(d, a0, a1, a2, a3, b0, b1) \
    asm volatile("mma.sync.aligned.m16n8k16.row.col.f32.f16.f16.f32 " \
        "{%0,%1,%2,%3},{%4,%5,%6,%7},{%8,%9},{%0,%1,%2,%3};" \
        : "+f"((d)[0]), "+f"((d)[1]), "+f"((d)[2]), "+f"((d)[3]) \
        : "r"(a0), "r"(a1), "r"(a2), "r"(a3), "r"(b0), "r"(b1))

// pack (x0 -> low half, x1 -> high half) into one fp16x2 register
static __device__ __forceinline__ uint32_t h2pack(float x0, float x1) {
    uint32_t h;
    asm("cvt.rn.f16x2.f32 %0, %1, %2;" : "=r"(h) : "f"(x1), "f"(x0));
    return h;
}

__device__ __forceinline__ float warpRedMax(float v) {
    #pragma unroll
    for (int o = 16; o > 0; o >>= 1) v = fmaxf(v, __shfl_xor_sync(0xffffffffu, v, o));
    return v;
}
__device__ __forceinline__ float warpRedSum(float v) {
    #pragma unroll
    for (int o = 16; o > 0; o >>= 1) v += __shfl_xor_sync(0xffffffffu, v, o);
    return v;
}

extern "C" __global__ void __launch_bounds__(NTHREADS, 4)
asp_kernel(const float* __restrict__ query,
           const float* __restrict__ keys,
           const int*   __restrict__ klw,
           const float* __restrict__ W1,
           const float* __restrict__ b1,
           const float* __restrict__ W2,
           const float* __restrict__ b2,
           const float* __restrict__ W3,
           const float* __restrict__ b3,
           float* __restrict__ out)
{
    extern __shared__ char sbase[];
    const uint32_t sb = smem_u32(sbase);

    float* qS   = (float*)(sbase + OFF_SC);          // 64
    float* qWbS = qS   + 64;                         // 64
    float* b2S  = qWbS + 64;                         // 32
    float* W3S  = b2S  + 32;                         // 32
    float* wS   = W3S  + 32;                         // 256 (also qWb-partial scratch)
    float* redS = wS   + 256;                        // 32

    const int b    = blockIdx.x;
    const int tid  = threadIdx.x;
    const int lane = tid & 31;
    const int warp = tid >> 5;

    const float* qg = query + (size_t)b * 64;
    const float* kg = keys  + (size_t)b * T_REAL * 64;

    int len;
    {
        const bool is64 = ((klw[1] | klw[3] | klw[5] | klw[7] | klw[9] | klw[11]) == 0);
        len = is64 ? klw[2 * b] : klw[b];
    }
    // blocks >= nblk produce only masked scores -> skip their GEMM entirely
    const int nblk = (len + 15) >> 4;
    const float b3v = b3[0];

    // ---- stage small operands ----
    if (tid < 64)       qS[tid]     = qg[tid];
    else if (tid < 96)  W3S[tid-64] = W3[tid-64];
    else if (tid < 128) b2S[tid-96] = b2[tid-96];
    __syncthreads();

    // ---- qWb partials: thread (g=tid>>6, j=tid&63) sums i in [16g,16g+16) ----
    {
        const int j = tid & 63, g = tid >> 6;
        float s = 0.f;
        #pragma unroll 4
        for (int i = 16 * g; i < 16 * g + 16; i++)
            s += qS[i] * (W1[i*64 + j] + W1[(128+i)*64 + j]);
        wS[tid] = s;
    }
    // ---- Weff^T fp16 (paired over i): WqT[j][i] ----
    for (int idx = tid; idx < 2048; idx += NTHREADS) {
        const int j = idx & 63, i0 = (idx >> 6) * 2;
        const float w0 = W1[(64+i0)*64 + j] - W1[(128+i0)*64 + j] + qS[i0]   * W1[(192+i0)*64 + j];
        const float w1 = W1[(65+i0)*64 + j] - W1[(129+i0)*64 + j] + qS[i0+1] * W1[(193+i0)*64 + j];
        *(uint32_t*)(sbase + OFF_WQ + j*ROWB + i0*2) = h2pack(w0, w1);
    }
    // ---- W2^T fp16: W2T[n][i] ----
    for (int idx = tid; idx < 1024; idx += NTHREADS) {
        const int n = idx & 31, i0 = (idx >> 5) * 2;
        *(uint32_t*)(sbase + OFF_W2 + n*ROWB + i0*2) =
            h2pack(W2[i0*32 + n], W2[(i0+1)*32 + n]);
    }
    __syncthreads();
    if (tid < 64)
        qWbS[tid] = b1[tid] + wS[tid] + wS[64+tid] + wS[128+tid] + wS[192+tid];
    __syncthreads();   // qWbS ready; wS free for score writes

    // ---- ldmatrix lane addressing ----
    const uint32_t laneR16 = lane & 15;
    const uint32_t laneC   = (lane >> 4) << 3;
    // B (x4, paired nt)
    const uint32_t bNt = (lane >> 4) & 1;
    const uint32_t bK  = ((lane >> 3) & 1) << 3;
    const uint32_t bR  = lane & 7;
    const uint32_t bBase = (uint32_t)(bNt * 8 + bR) * ROWB + bK * 2;

    // ---- stage BOTH assigned key blocks into dedicated strips ----
    // (unconditional: the final weighted sum always reads all 200 rows;
    //  len==0 requires the full uniform average)
    #pragma unroll 1
    for (int bi = 0; bi < 2; bi++) {
        const int blk = warp + bi * 8;
        if (blk * 16 >= T_REAL) break;          // blocks 13..15 don't exist
        char* stp = sbase + OFF_K + blk * WSTRIP;
        #pragma unroll
        for (int it = 0; it < 8; it++) {
            const int idx = it * 32 + lane;
            const int row = idx >> 4, q4 = idx & 15;
            const int t = blk * 16 + row;
            float4 v = make_float4(0.f, 0.f, 0.f, 0.f);
            if (t < T_REAL) v = ((const float4*)kg)[t * 16 + q4];
            *(uint2*)(stp + row*ROWB + q4*8) =
                make_uint2(h2pack(v.x, v.y), h2pack(v.z, v.w));
        }
    }
    __syncwarp();

    // ================= per-warp independent 16-row blocks =================
    // skip blocks whose every row is masked (blk >= nblk): their scores are
    // overwritten with MASK_VAL before softmax and never read.
    #pragma unroll 1
    for (int bi = 0; bi < 2; bi++) {
        const int blk = warp + bi * 8;
        if (blk * 16 >= T_REAL) break;
        if (blk >= nblk) continue;
        const uint32_t myK = sb + OFF_K + blk * WSTRIP;

        // ---- layer 1: C1[16 x 64] ----
        float c1[8][4];
        #pragma unroll
        for (int q = 0; q < 8; q++)
            #pragma unroll
            for (int x = 0; x < 4; x++) c1[q][x] = 0.f;

        #pragma unroll
        for (int kk = 0; kk < 4; kk++) {
            const uint32_t aoff = laneR16 * ROWB + (kk*16 + laneC) * 2;
            uint32_t aH[4];
            LDMX4(aH, myK + aoff);
            #pragma unroll
            for (int pp = 0; pp < 4; pp++) {           // nt pairs
                const uint32_t boff = (uint32_t)(pp * 16) * ROWB + kk * 32 + bBase;
                uint32_t bH[4];
                LDMX4(bH, sb + OFF_WQ + boff);
                MMA16816(c1[pp*2+0], aH[0], aH[1], aH[2], aH[3], bH[0], bH[1]);
                MMA16816(c1[pp*2+1], aH[0], aH[1], aH[2], aH[3], bH[2], bH[3]);
            }
        }

        // ---- epilogue 1: h1 = relu(C1 + qWb) -> fp16 -> layer-2 A frags ----
        uint32_t a2[4][4];
        #pragma unroll
        for (int nt = 0; nt < 8; nt++) {
            const int n0 = nt*8 + 2*(lane & 3);
            const float x0 = fmaxf(c1[nt][0] + qWbS[n0],   0.f);
            const float x1 = fmaxf(c1[nt][1] + qWbS[n0+1], 0.f);
            const float x2 = fmaxf(c1[nt][2] + qWbS[n0],   0.f);
            const float x3 = fmaxf(c1[nt][3] + qWbS[n0+1], 0.f);
            const int kk2 = nt >> 1, s = (nt & 1) * 2;
            a2[kk2][s+0] = h2pack(x0, x1);
            a2[kk2][s+1] = h2pack(x2, x3);
        }

        // ---- layer 2: C2[16 x 32] ----
        float c2[4][4];
        #pragma unroll
        for (int q = 0; q < 4; q++)
            #pragma unroll
            for (int x = 0; x < 4; x++) c2[q][x] = 0.f;

        #pragma unroll
        for (int kk = 0; kk < 4; kk++) {
            #pragma unroll
            for (int pp = 0; pp < 2; pp++) {           // nt pairs (N=32)
                const uint32_t boff = (uint32_t)(pp * 16) * ROWB + kk * 32 + bBase;
                uint32_t bH[4];
                LDMX4(bH, sb + OFF_W2 + boff);
                MMA16816(c2[pp*2+0], a2[kk][0], a2[kk][1], a2[kk][2], a2[kk][3], bH[0], bH[1]);
                MMA16816(c2[pp*2+1], a2[kk][0], a2[kk][1], a2[kk][2], a2[kk][3], bH[2], bH[3]);
            }
        }

        // ---- epilogue 2: score = relu(C2 + b2) . W3 (quad reduce) ----
        float p0 = 0.f, p1 = 0.f;
        #pragma unroll
        for (int nt = 0; nt < 4; nt++) {
            const int n0 = nt*8 + 2*(lane & 3);
            const float w0 = W3S[n0], w1 = W3S[n0+1];
            const float bb0 = b2S[n0], bb1 = b2S[n0+1];
            p0 += fmaxf(c2[nt][0] + bb0, 0.f) * w0 + fmaxf(c2[nt][1] + bb1, 0.f) * w1;
            p1 += fmaxf(c2[nt][2] + bb0, 0.f) * w0 + fmaxf(c2[nt][3] + bb1, 0.f) * w1;
        }
        p0 += __shfl_xor_sync(0xffffffffu, p0, 1);
        p0 += __shfl_xor_sync(0xffffffffu, p0, 2);
        p1 += __shfl_xor_sync(0xffffffffu, p1, 1);
        p1 += __shfl_xor_sync(0xffffffffu, p1, 2);
        if ((lane & 3) == 0) {
            wS[blk*16 + (lane >> 2)]     = p0 + b3v;
            wS[blk*16 + (lane >> 2) + 8] = p1 + b3v;
        }
    }
    __syncthreads();

    // ---- mask + softmax over wS ----
    // for t >= len, wS may be stale/garbage: always overwritten with MASK_VAL here
    float sc;
    if (tid < T_REAL) sc = (tid < len) ? wS[tid] : MASK_VAL_F;
    else              sc = -FLT_MAX;

    float m = warpRedMax(sc);
    if ((tid & 31) == 0) redS[tid >> 5] = m;
    __syncthreads();
    float bm = redS[0];
    #pragma unroll
    for (int w = 1; w < 8; w++) bm = fmaxf(bm, redS[w]);
    __syncthreads();
    const float e = (tid < T_REAL) ? expf(sc - bm) : 0.f;
    float s1 = warpRedSum(e);
    if ((tid & 31) == 0) redS[tid >> 5] = s1;
    __syncthreads();
    float bs = 0.f;
    #pragma unroll
    for (int w = 0; w < 8; w++) bs += redS[w];
    wS[tid] = e * (1.0f / bs);
    __syncthreads();

    // ---- weighted sum from SMEM fp16 keys: out[e] = sum_t w_t * k16[t][e] ----
    // strip layout linearizes: addr = OFF_K + t*ROWB + e*2
    // full range kept: weights are exactly 0 beyond len (and len==0 -> uniform)
    float* scr = (float*)(sbase + OFF_WQ);   // reuse as fp32 scratch (256 floats)
    {
        const int e_ = tid & 63;
        const int g  = tid >> 6;
        const char* kbase = sbase + OFF_K + e_ * 2;
        float acc0 = 0.f, acc1 = 0.f;
        #pragma unroll 4
        for (int t = g; t < 192; t += 8) {
            acc0 += wS[t]     * __half2float(*(const __half*)(kbase + t * ROWB));
            acc1 += wS[t + 4] * __half2float(*(const __half*)(kbase + (t + 4) * ROWB));
        }
        acc0 += wS[192 + g] * __half2float(*(const __half*)(kbase + (192 + g) * ROWB));
        acc1 += wS[196 + g] * __half2float(*(const __half*)(kbase + (196 + g) * ROWB));
        scr[g * 64 + e_] = acc0 + acc1;
    }
    __syncthreads();
    if (tid < 64)
        out[(size_t)b * 64 + tid] =
            scr[tid] + scr[64 + tid] + scr[128 + tid] + scr[192 + tid];
}

extern "C" void kernel_launch(void* const* d_in, const int* in_sizes, int n_in,
                              void* d_out, int out_size) {
    const float* query = (const float*)d_in[0];
    const float* keys  = (const float*)d_in[1];
    const int*   klen  = (const int*)  d_in[2];
    const float* W1    = (const float*)d_in[3];
    const float* b1    = (const float*)d_in[4];
    const float* W2    = (const float*)d_in[5];
    const float* b2    = (const float*)d_in[6];
    const float* W3    = (const float*)d_in[7];
    const float* b3    = (const float*)d_in[8];
    float* out = (float*)d_out;

    const int B = in_sizes[0] / 64;

    cudaFuncSetAttribute(asp_kernel,
                         cudaFuncAttributeMaxDynamicSharedMemorySize,
                         SMEM_TOTAL);

    asp_kernel<<<B, NTHREADS, SMEM_TOTAL>>>(query, keys, klen,
                                            W1, b1, W2, b2, W3, b3, out);
}

// round 15
// speedup vs baseline: 1.4525x; 1.1478x over previous
#include <cuda_runtime.h>
#include <cuda_fp16.h>
#include <stdint.h>
#include <math.h>
#include <float.h>

#define NTHREADS   256
#define T_REAL     200
#define MASK_VAL_F (-4294967296.0f)   // jnp.float32(-2**32+1) rounds to -2^32

// fp16 SMEM tiles, row stride 72 elements (144 B: 16B-aligned, conflict-free ldmatrix)
#define ROWB       144
#define WSTRIP     (16 * ROWB)             // 2304 B per 16-row block strip
#define NSTRIPS    13                      // ceil(200/16)

// ---- SMEM byte offsets ----
#define OFF_K     0                        // keys fp16, 13 block strips : 29952
#define OFF_WQ    (NSTRIPS * WSTRIP)       // Weff^T fp16 [64][72] : 9216
#define OFF_W2    (OFF_WQ + 9216)          // W2^T  fp16 [32][72]  : 4608
#define OFF_SC    (OFF_W2 + 4608)          // fp32 scalars
#define SMEM_TOTAL (OFF_SC + 1920)         // 45696 B -> 4 CTAs/SM

// ---------------- PTX helpers (baseline, no sm_103a-only features) ----------------
static __device__ __forceinline__ uint32_t smem_u32(const void* p) {
    uint32_t a;
    asm("{ .reg .u64 t; cvta.to.shared.u64 t, %1; cvt.u32.u64 %0, t; }" : "=r"(a) : "l"(p));
    return a;
}

#define LDMX4(r, addr) \
    asm volatile("ldmatrix.sync.aligned.m8n8.x4.shared.b16 {%0,%1,%2,%3}, [%4];" \
        : "=r"((r)[0]), "=r"((r)[1]), "=r"((r)[2]), "=r"((r)[3]) : "r"(addr))

#define MMA16816(d, a0, a1, a2, a3, b0, b1) \
    asm volatile("mma.sync.aligned.m16n8k16.row.col.f32.f16.f16.f32 " \
        "{%0,%1,%2,%3},{%4,%5,%6,%7},{%8,%9},{%0,%1,%2,%3};" \
        : "+f"((d)[0]), "+f"((d)[1]), "+f"((d)[2]), "+f"((d)[3]) \
        : "r"(a0), "r"(a1), "r"(a2), "r"(a3), "r"(b0), "r"(b1))

// pack (x0 -> low half, x1 -> high half) into one fp16x2 register
static __device__ __forceinline__ uint32_t h2pack(float x0, float x1) {
    uint32_t h;
    asm("cvt.rn.f16x2.f32 %0, %1, %2;" : "=r"(h) : "f"(x1), "f"(x0));
    return h;
}

__device__ __forceinline__ float warpRedMax(float v) {
    #pragma unroll
    for (int o = 16; o > 0; o >>= 1) v = fmaxf(v, __shfl_xor_sync(0xffffffffu, v, o));
    return v;
}
__device__ __forceinline__ float warpRedSum(float v) {
    #pragma unroll
    for (int o = 16; o > 0; o >>= 1) v += __shfl_xor_sync(0xffffffffu, v, o);
    return v;
}

extern "C" __global__ void __launch_bounds__(NTHREADS, 4)
asp_kernel(const float* __restrict__ query,
           const float* __restrict__ keys,
           const int*   __restrict__ klw,
           const float* __restrict__ W1,
           const float* __restrict__ b1,
           const float* __restrict__ W2,
           const float* __restrict__ b2,
           const float* __restrict__ W3,
           const float* __restrict__ b3,
           float* __restrict__ out)
{
    extern __shared__ char sbase[];
    const uint32_t sb = smem_u32(sbase);

    float* qS   = (float*)(sbase + OFF_SC);          // 64
    float* qWbS = qS   + 64;                         // 64
    float* b2S  = qWbS + 64;                         // 32
    float* W3S  = b2S  + 32;                         // 32
    float* wS   = W3S  + 32;                         // 256 (also qWb-partial scratch)
    float* redS = wS   + 256;                        // 32

    const int b    = blockIdx.x;
    const int tid  = threadIdx.x;
    const int lane = tid & 31;
    const int warp = tid >> 5;

    const float* qg = query + (size_t)b * 64;
    const float* kg = keys  + (size_t)b * T_REAL * 64;

    int len;
    {
        const bool is64 = ((klw[1] | klw[3] | klw[5] | klw[7] | klw[9] | klw[11]) == 0);
        len = is64 ? klw[2 * b] : klw[b];
    }
    if (len > T_REAL) len = T_REAL;
    // scored blocks (GEMM needed): scores for t >= len are masked away
    const int nblk = (len + 15) >> 4;
    // rows needed by the weighted sum: softmax weights are exactly 0 for
    // t >= len when len > 0; len == 0 gives uniform 1/200 over ALL rows
    const int lenW  = (len == 0) ? T_REAL : len;
    const int nblkS = (lenW + 15) >> 4;      // strips that must be staged
    const float b3v = b3[0];

    // ---- stage small operands ----
    if (tid < 64)       qS[tid]     = qg[tid];
    else if (tid < 96)  W3S[tid-64] = W3[tid-64];
    else if (tid < 128) b2S[tid-96] = b2[tid-96];
    __syncthreads();

    // ---- qWb partials: thread (g=tid>>6, j=tid&63) sums i in [16g,16g+16) ----
    {
        const int j = tid & 63, g = tid >> 6;
        float s = 0.f;
        #pragma unroll 4
        for (int i = 16 * g; i < 16 * g + 16; i++)
            s += qS[i] * (W1[i*64 + j] + W1[(128+i)*64 + j]);
        wS[tid] = s;
    }
    // ---- Weff^T fp16 (paired over i): WqT[j][i] ----
    for (int idx = tid; idx < 2048; idx += NTHREADS) {
        const int j = idx & 63, i0 = (idx >> 6) * 2;
        const float w0 = W1[(64+i0)*64 + j] - W1[(128+i0)*64 + j] + qS[i0]   * W1[(192+i0)*64 + j];
        const float w1 = W1[(65+i0)*64 + j] - W1[(129+i0)*64 + j] + qS[i0+1] * W1[(193+i0)*64 + j];
        *(uint32_t*)(sbase + OFF_WQ + j*ROWB + i0*2) = h2pack(w0, w1);
    }
    // ---- W2^T fp16: W2T[n][i] ----
    for (int idx = tid; idx < 1024; idx += NTHREADS) {
        const int n = idx & 31, i0 = (idx >> 5) * 2;
        *(uint32_t*)(sbase + OFF_W2 + n*ROWB + i0*2) =
            h2pack(W2[i0*32 + n], W2[(i0+1)*32 + n]);
    }
    __syncthreads();
    if (tid < 64)
        qWbS[tid] = b1[tid] + wS[tid] + wS[64+tid] + wS[128+tid] + wS[192+tid];
    __syncthreads();   // qWbS ready; wS free for score writes

    // ---- ldmatrix lane addressing ----
    const uint32_t laneR16 = lane & 15;
    const uint32_t laneC   = (lane >> 4) << 3;
    // B (x4, paired nt)
    const uint32_t bNt = (lane >> 4) & 1;
    const uint32_t bK  = ((lane >> 3) & 1) << 3;
    const uint32_t bR  = lane & 7;
    const uint32_t bBase = (uint32_t)(bNt * 8 + bR) * ROWB + bK * 2;

    // ---- stage only the strips that are actually read (blk < nblkS) ----
    #pragma unroll 1
    for (int bi = 0; bi < 2; bi++) {
        const int blk = warp + bi * 8;
        if (blk >= nblkS) continue;
        char* stp = sbase + OFF_K + blk * WSTRIP;
        #pragma unroll
        for (int it = 0; it < 8; it++) {
            const int idx = it * 32 + lane;
            const int row = idx >> 4, q4 = idx & 15;
            const int t = blk * 16 + row;
            float4 v = make_float4(0.f, 0.f, 0.f, 0.f);
            if (t < T_REAL) v = ((const float4*)kg)[t * 16 + q4];
            *(uint2*)(stp + row*ROWB + q4*8) =
                make_uint2(h2pack(v.x, v.y), h2pack(v.z, v.w));
        }
    }
    __syncwarp();

    // ================= per-warp independent 16-row blocks =================
    // skip blocks whose every row is masked (blk >= nblk)
    #pragma unroll 1
    for (int bi = 0; bi < 2; bi++) {
        const int blk = warp + bi * 8;
        if (blk >= nblk) continue;
        const uint32_t myK = sb + OFF_K + blk * WSTRIP;

        // ---- layer 1: C1[16 x 64] ----
        float c1[8][4];
        #pragma unroll
        for (int q = 0; q < 8; q++)
            #pragma unroll
            for (int x = 0; x < 4; x++) c1[q][x] = 0.f;

        #pragma unroll
        for (int kk = 0; kk < 4; kk++) {
            const uint32_t aoff = laneR16 * ROWB + (kk*16 + laneC) * 2;
            uint32_t aH[4];
            LDMX4(aH, myK + aoff);
            #pragma unroll
            for (int pp = 0; pp < 4; pp++) {           // nt pairs
                const uint32_t boff = (uint32_t)(pp * 16) * ROWB + kk * 32 + bBase;
                uint32_t bH[4];
                LDMX4(bH, sb + OFF_WQ + boff);
                MMA16816(c1[pp*2+0], aH[0], aH[1], aH[2], aH[3], bH[0], bH[1]);
                MMA16816(c1[pp*2+1], aH[0], aH[1], aH[2], aH[3], bH[2], bH[3]);
            }
        }

        // ---- epilogue 1: h1 = relu(C1 + qWb) -> fp16 -> layer-2 A frags ----
        uint32_t a2[4][4];
        #pragma unroll
        for (int nt = 0; nt < 8; nt++) {
            const int n0 = nt*8 + 2*(lane & 3);
            const float x0 = fmaxf(c1[nt][0] + qWbS[n0],   0.f);
            const float x1 = fmaxf(c1[nt][1] + qWbS[n0+1], 0.f);
            const float x2 = fmaxf(c1[nt][2] + qWbS[n0],   0.f);
            const float x3 = fmaxf(c1[nt][3] + qWbS[n0+1], 0.f);
            const int kk2 = nt >> 1, s = (nt & 1) * 2;
            a2[kk2][s+0] = h2pack(x0, x1);
            a2[kk2][s+1] = h2pack(x2, x3);
        }

        // ---- layer 2: C2[16 x 32] ----
        float c2[4][4];
        #pragma unroll
        for (int q = 0; q < 4; q++)
            #pragma unroll
            for (int x = 0; x < 4; x++) c2[q][x] = 0.f;

        #pragma unroll
        for (int kk = 0; kk < 4; kk++) {
            #pragma unroll
            for (int pp = 0; pp < 2; pp++) {           // nt pairs (N=32)
                const uint32_t boff = (uint32_t)(pp * 16) * ROWB + kk * 32 + bBase;
                uint32_t bH[4];
                LDMX4(bH, sb + OFF_W2 + boff);
                MMA16816(c2[pp*2+0], a2[kk][0], a2[kk][1], a2[kk][2], a2[kk][3], bH[0], bH[1]);
                MMA16816(c2[pp*2+1], a2[kk][0], a2[kk][1], a2[kk][2], a2[kk][3], bH[2], bH[3]);
            }
        }

        // ---- epilogue 2: score = relu(C2 + b2) . W3 (quad reduce) ----
        float p0 = 0.f, p1 = 0.f;
        #pragma unroll
        for (int nt = 0; nt < 4; nt++) {
            const int n0 = nt*8 + 2*(lane & 3);
            const float w0 = W3S[n0], w1 = W3S[n0+1];
            const float bb0 = b2S[n0], bb1 = b2S[n0+1];
            p0 += fmaxf(c2[nt][0] + bb0, 0.f) * w0 + fmaxf(c2[nt][1] + bb1, 0.f) * w1;
            p1 += fmaxf(c2[nt][2] + bb0, 0.f) * w0 + fmaxf(c2[nt][3] + bb1, 0.f) * w1;
        }
        p0 += __shfl_xor_sync(0xffffffffu, p0, 1);
        p0 += __shfl_xor_sync(0xffffffffu, p0, 2);
        p1 += __shfl_xor_sync(0xffffffffu, p1, 1);
        p1 += __shfl_xor_sync(0xffffffffu, p1, 2);
        if ((lane & 3) == 0) {
            wS[blk*16 + (lane >> 2)]     = p0 + b3v;
            wS[blk*16 + (lane >> 2) + 8] = p1 + b3v;
        }
    }
    __syncthreads();

    // ---- mask + softmax over wS ----
    // for t >= len, wS may be stale/garbage: always overwritten with MASK_VAL here.
    // len == 0: every score becomes MASK -> e = 1 for all t -> uniform 1/200.
    float sc;
    if (tid < T_REAL) sc = (tid < len) ? wS[tid] : MASK_VAL_F;
    else              sc = -FLT_MAX;

    float m = warpRedMax(sc);
    if ((tid & 31) == 0) redS[tid >> 5] = m;
    __syncthreads();
    float bm = redS[0];
    #pragma unroll
    for (int w = 1; w < 8; w++) bm = fmaxf(bm, redS[w]);
    __syncthreads();
    const float e = (tid < T_REAL) ? expf(sc - bm) : 0.f;
    float s1 = warpRedSum(e);
    if ((tid & 31) == 0) redS[tid >> 5] = s1;
    __syncthreads();
    float bs = 0.f;
    #pragma unroll
    for (int w = 0; w < 8; w++) bs += redS[w];
    wS[tid] = e * (1.0f / bs);
    __syncthreads();

    // ---- weighted sum from SMEM fp16 keys, bounded by lenW ----
    // weights are exactly 0 for t >= lenW; strips >= nblkS never staged/read
    float* scr = (float*)(sbase + OFF_WQ);   // reuse as fp32 scratch (256 floats)
    {
        const int e_ = tid & 63;
        const int g  = tid >> 6;
        const char* kbase = sbase + OFF_K + e_ * 2;
        float acc0 = 0.f, acc1 = 0.f;
        int t = g;
        #pragma unroll 2
        for (; t + 4 < lenW; t += 8) {
            acc0 += wS[t]     * __half2float(*(const __half*)(kbase + t * ROWB));
            acc1 += wS[t + 4] * __half2float(*(const __half*)(kbase + (t + 4) * ROWB));
        }
        if (t < lenW)
            acc0 += wS[t] * __half2float(*(const __half*)(kbase + t * ROWB));
        scr[g * 64 + e_] = acc0 + acc1;
    }
    __syncthreads();
    if (tid < 64)
        out[(size_t)b * 64 + tid] =
            scr[tid] + scr[64 + tid] + scr[128 + tid] + scr[192 + tid];
}

extern "C" void kernel_launch(void* const* d_in, const int* in_sizes, int n_in,
                              void* d_out, int out_size) {
    const float* query = (const float*)d_in[0];
    const float* keys  = (const float*)d_in[1];
    const int*   klen  = (const int*)  d_in[2];
    const float* W1    = (const float*)d_in[3];
    const float* b1    = (const float*)d_in[4];
    const float* W2    = (const float*)d_in[5];
    const float* b2    = (const float*)d_in[6];
    const float* W3    = (const float*)d_in[7];
    const float* b3    = (const float*)d_in[8];
    float* out = (float*)d_out;

    const int B = in_sizes[0] / 64;

    cudaFuncSetAttribute(asp_kernel,
                         cudaFuncAttributeMaxDynamicSharedMemorySize,
                         SMEM_TOTAL);

    asp_kernel<<<B, NTHREADS, SMEM_TOTAL>>>(query, keys, klen,
                                            W1, b1, W2, b2, W3, b3, out);
}

// round 16
// speedup vs baseline: 1.4808x; 1.0194x over previous
#include <cuda_runtime.h>
#include <cuda_fp16.h>
#include <stdint.h>
#include <math.h>
#include <float.h>

#define NTHREADS   256
#define T_REAL     200
#define MASK_VAL_F (-4294967296.0f)   // jnp.float32(-2**32+1) rounds to -2^32

// fp16 SMEM tiles, row stride 72 elements (144 B: 16B-aligned, conflict-free ldmatrix)
#define ROWB       144
#define WSTRIP     (16 * ROWB)             // 2304 B per 16-row block strip
#define NSTRIPS    13                      // ceil(200/16)

// ---- SMEM byte offsets ----
#define OFF_K     0                        // keys fp16, 13 block strips : 29952
#define OFF_WQ    (NSTRIPS * WSTRIP)       // Weff^T fp16 [64][72] : 9216
#define OFF_W2    (OFF_WQ + 9216)          // W2^T  fp16 [32][72]  : 4608
#define OFF_SC    (OFF_W2 + 4608)          // fp32 scalars
#define SMEM_TOTAL (OFF_SC + 1920)         // 45696 B -> 4 CTAs/SM

// ---------------- PTX helpers (baseline, no sm_103a-only features) ----------------
static __device__ __forceinline__ uint32_t smem_u32(const void* p) {
    uint32_t a;
    asm("{ .reg .u64 t; cvta.to.shared.u64 t, %1; cvt.u32.u64 %0, t; }" : "=r"(a) : "l"(p));
    return a;
}

#define LDMX4(r, addr) \
    asm volatile("ldmatrix.sync.aligned.m8n8.x4.shared.b16 {%0,%1,%2,%3}, [%4];" \
        : "=r"((r)[0]), "=r"((r)[1]), "=r"((r)[2]), "=r"((r)[3]) : "r"(addr))

#define MMA16816(d, a0, a1, a2, a3, b0, b1) \
    asm volatile("mma.sync.aligned.m16n8k16.row.col.f32.f16.f16.f32 " \
        "{%0,%1,%2,%3},{%4,%5,%6,%7},{%8,%9},{%0,%1,%2,%3};" \
        : "+f"((d)[0]), "+f"((d)[1]), "+f"((d)[2]), "+f"((d)[3]) \
        : "r"(a0), "r"(a1), "r"(a2), "r"(a3), "r"(b0), "r"(b1))

// pack (x0 -> low half, x1 -> high half) into one fp16x2 register
static __device__ __forceinline__ uint32_t h2pack(float x0, float x1) {
    uint32_t h;
    asm("cvt.rn.f16x2.f32 %0, %1, %2;" : "=r"(h) : "f"(x1), "f"(x0));
    return h;
}

__device__ __forceinline__ float warpRedMax(float v) {
    #pragma unroll
    for (int o = 16; o > 0; o >>= 1) v = fmaxf(v, __shfl_xor_sync(0xffffffffu, v, o));
    return v;
}
__device__ __forceinline__ float warpRedSum(float v) {
    #pragma unroll
    for (int o = 16; o > 0; o >>= 1) v += __shfl_xor_sync(0xffffffffu, v, o);
    return v;
}

extern "C" __global__ void __launch_bounds__(NTHREADS, 4)
asp_kernel(const float* __restrict__ query,
           const float* __restrict__ keys,
           const int*   __restrict__ klw,
           const float* __restrict__ W1,
           const float* __restrict__ b1,
           const float* __restrict__ W2,
           const float* __restrict__ b2,
           const float* __restrict__ W3,
           const float* __restrict__ b3,
           float* __restrict__ out)
{
    extern __shared__ char sbase[];
    const uint32_t sb = smem_u32(sbase);

    float* qWbS = (float*)(sbase + OFF_SC);          // 64
    float* b2S  = qWbS + 64;                         // 32
    float* W3S  = b2S  + 32;                         // 32
    float* wS   = W3S  + 32;                         // 256 (also qWb-partial scratch)

    const int b    = blockIdx.x;
    const int tid  = threadIdx.x;
    const int lane = tid & 31;
    const int warp = tid >> 5;

    const float* qg = query + (size_t)b * 64;
    const float* kg = keys  + (size_t)b * T_REAL * 64;

    int len;
    {
        const bool is64 = ((klw[1] | klw[3] | klw[5] | klw[7] | klw[9] | klw[11]) == 0);
        len = is64 ? klw[2 * b] : klw[b];
    }
    if (len > T_REAL) len = T_REAL;
    const int nblk = (len + 15) >> 4;          // blocks needing GEMM
    const int lenW  = (len == 0) ? T_REAL : len;
    const int nblkS = (lenW + 15) >> 4;        // strips needing staging
    const float b3v = b3[0];

    // ---- small operands (no barrier; consumed only after later syncs) ----
    if (tid < 32)       W3S[tid]    = W3[tid];
    else if (tid < 64)  b2S[tid-32] = b2[tid-32];

    // ---- keys staging FIRST: DRAM latency overlaps the weight transform ----
    #pragma unroll 1
    for (int bi = 0; bi < 2; bi++) {
        const int blk = warp + bi * 8;
        if (blk >= nblkS) continue;
        char* stp = sbase + OFF_K + blk * WSTRIP;
        #pragma unroll
        for (int it = 0; it < 8; it++) {
            const int idx = it * 32 + lane;
            const int row = idx >> 4, q4 = idx & 15;
            const int t = blk * 16 + row;
            float4 v = make_float4(0.f, 0.f, 0.f, 0.f);
            if (t < T_REAL) v = ((const float4*)kg)[t * 16 + q4];
            *(uint2*)(stp + row*ROWB + q4*8) =
                make_uint2(h2pack(v.x, v.y), h2pack(v.z, v.w));
        }
    }

    // ---- Weff^T fp16 (paired over i), q read straight from global ----
    for (int idx = tid; idx < 2048; idx += NTHREADS) {
        const int j = idx & 63, i0 = (idx >> 6) * 2;
        const float q0 = __ldg(qg + i0), q1 = __ldg(qg + i0 + 1);
        const float w0 = W1[(64+i0)*64 + j] - W1[(128+i0)*64 + j] + q0 * W1[(192+i0)*64 + j];
        const float w1 = W1[(65+i0)*64 + j] - W1[(129+i0)*64 + j] + q1 * W1[(193+i0)*64 + j];
        *(uint32_t*)(sbase + OFF_WQ + j*ROWB + i0*2) = h2pack(w0, w1);
    }
    // ---- W2^T fp16 ----
    for (int idx = tid; idx < 1024; idx += NTHREADS) {
        const int n = idx & 31, i0 = (idx >> 5) * 2;
        *(uint32_t*)(sbase + OFF_W2 + n*ROWB + i0*2) =
            h2pack(W2[i0*32 + n], W2[(i0+1)*32 + n]);
    }
    // ---- qWb partials: thread (g=tid>>6, j=tid&63) sums i in [16g,16g+16) ----
    {
        const int j = tid & 63, g = tid >> 6;
        float s = 0.f;
        #pragma unroll 4
        for (int i = 16 * g; i < 16 * g + 16; i++)
            s += __ldg(qg + i) * (W1[i*64 + j] + W1[(128+i)*64 + j]);
        wS[tid] = s;
    }
    __syncthreads();                           // A: transform + partials done
    if (tid < 64)
        qWbS[tid] = b1[tid] + wS[tid] + wS[64+tid] + wS[128+tid] + wS[192+tid];
    __syncthreads();                           // B: qWbS ready; wS free

    // ---- ldmatrix lane addressing ----
    const uint32_t laneR16 = lane & 15;
    const uint32_t laneC   = (lane >> 4) << 3;
    const uint32_t bNt = (lane >> 4) & 1;
    const uint32_t bK  = ((lane >> 3) & 1) << 3;
    const uint32_t bR  = lane & 7;
    const uint32_t bBase = (uint32_t)(bNt * 8 + bR) * ROWB + bK * 2;

    // ================= per-warp independent 16-row blocks =================
    #pragma unroll 1
    for (int bi = 0; bi < 2; bi++) {
        const int blk = warp + bi * 8;
        if (blk >= nblk) continue;
        const uint32_t myK = sb + OFF_K + blk * WSTRIP;

        // ---- layer 1: C1[16 x 64] ----
        float c1[8][4];
        #pragma unroll
        for (int q = 0; q < 8; q++)
            #pragma unroll
            for (int x = 0; x < 4; x++) c1[q][x] = 0.f;

        #pragma unroll
        for (int kk = 0; kk < 4; kk++) {
            const uint32_t aoff = laneR16 * ROWB + (kk*16 + laneC) * 2;
            uint32_t aH[4];
            LDMX4(aH, myK + aoff);
            #pragma unroll
            for (int pp = 0; pp < 4; pp++) {           // nt pairs
                const uint32_t boff = (uint32_t)(pp * 16) * ROWB + kk * 32 + bBase;
                uint32_t bH[4];
                LDMX4(bH, sb + OFF_WQ + boff);
                MMA16816(c1[pp*2+0], aH[0], aH[1], aH[2], aH[3], bH[0], bH[1]);
                MMA16816(c1[pp*2+1], aH[0], aH[1], aH[2], aH[3], bH[2], bH[3]);
            }
        }

        // ---- epilogue 1: h1 = relu(C1 + qWb) -> fp16 -> layer-2 A frags ----
        uint32_t a2[4][4];
        #pragma unroll
        for (int nt = 0; nt < 8; nt++) {
            const int n0 = nt*8 + 2*(lane & 3);
            const float x0 = fmaxf(c1[nt][0] + qWbS[n0],   0.f);
            const float x1 = fmaxf(c1[nt][1] + qWbS[n0+1], 0.f);
            const float x2 = fmaxf(c1[nt][2] + qWbS[n0],   0.f);
            const float x3 = fmaxf(c1[nt][3] + qWbS[n0+1], 0.f);
            const int kk2 = nt >> 1, s = (nt & 1) * 2;
            a2[kk2][s+0] = h2pack(x0, x1);
            a2[kk2][s+1] = h2pack(x2, x3);
        }

        // ---- layer 2: C2[16 x 32] ----
        float c2[4][4];
        #pragma unroll
        for (int q = 0; q < 4; q++)
            #pragma unroll
            for (int x = 0; x < 4; x++) c2[q][x] = 0.f;

        #pragma unroll
        for (int kk = 0; kk < 4; kk++) {
            #pragma unroll
            for (int pp = 0; pp < 2; pp++) {           // nt pairs (N=32)
                const uint32_t boff = (uint32_t)(pp * 16) * ROWB + kk * 32 + bBase;
                uint32_t bH[4];
                LDMX4(bH, sb + OFF_W2 + boff);
                MMA16816(c2[pp*2+0], a2[kk][0], a2[kk][1], a2[kk][2], a2[kk][3], bH[0], bH[1]);
                MMA16816(c2[pp*2+1], a2[kk][0], a2[kk][1], a2[kk][2], a2[kk][3], bH[2], bH[3]);
            }
        }

        // ---- epilogue 2: score = relu(C2 + b2) . W3 (quad reduce) ----
        float p0 = 0.f, p1 = 0.f;
        #pragma unroll
        for (int nt = 0; nt < 4; nt++) {
            const int n0 = nt*8 + 2*(lane & 3);
            const float w0 = W3S[n0], w1 = W3S[n0+1];
            const float bb0 = b2S[n0], bb1 = b2S[n0+1];
            p0 += fmaxf(c2[nt][0] + bb0, 0.f) * w0 + fmaxf(c2[nt][1] + bb1, 0.f) * w1;
            p1 += fmaxf(c2[nt][2] + bb0, 0.f) * w0 + fmaxf(c2[nt][3] + bb1, 0.f) * w1;
        }
        p0 += __shfl_xor_sync(0xffffffffu, p0, 1);
        p0 += __shfl_xor_sync(0xffffffffu, p0, 2);
        p1 += __shfl_xor_sync(0xffffffffu, p1, 1);
        p1 += __shfl_xor_sync(0xffffffffu, p1, 2);
        if ((lane & 3) == 0) {
            wS[blk*16 + (lane >> 2)]     = p0 + b3v;
            wS[blk*16 + (lane >> 2) + 8] = p1 + b3v;
        }
    }
    __syncthreads();                           // C: scores ready

    // ---- single-warp softmax (warp 0 holds all 256 slots in regs) ----
    // t >= len -> MASK (len==0 -> all MASK -> uniform 1/200); t >= 200 -> excluded
    if (warp == 0) {
        float v[8];
        float mx = -FLT_MAX;
        #pragma unroll
        for (int i = 0; i < 8; i++) {
            const int t = lane + 32 * i;
            float s;
            if (t < T_REAL) s = (t < len) ? wS[t] : MASK_VAL_F;
            else            s = -FLT_MAX;
            v[i] = s;
            mx = fmaxf(mx, s);
        }
        mx = warpRedMax(mx);
        float sum = 0.f;
        #pragma unroll
        for (int i = 0; i < 8; i++) {
            const int t = lane + 32 * i;
            const float e = (t < T_REAL) ? expf(v[i] - mx) : 0.f;
            v[i] = e;
            sum += e;
        }
        sum = warpRedSum(sum);
        const float inv = 1.0f / sum;
        #pragma unroll
        for (int i = 0; i < 8; i++)
            wS[lane + 32 * i] = v[i] * inv;
    }
    __syncthreads();                           // D: weights ready

    // ---- weighted sum from SMEM fp16 keys, bounded by lenW ----
    float* scr = (float*)(sbase + OFF_WQ);     // reuse as fp32 scratch (256 floats)
    {
        const int e_ = tid & 63;
        const int g  = tid >> 6;
        const char* kbase = sbase + OFF_K + e_ * 2;
        float acc0 = 0.f, acc1 = 0.f;
        int t = g;
        #pragma unroll 2
        for (; t + 4 < lenW; t += 8) {
            acc0 += wS[t]     * __half2float(*(const __half*)(kbase + t * ROWB));
            acc1 += wS[t + 4] * __half2float(*(const __half*)(kbase + (t + 4) * ROWB));
        }
        if (t < lenW)
            acc0 += wS[t] * __half2float(*(const __half*)(kbase + t * ROWB));
        scr[g * 64 + e_] = acc0 + acc1;
    }
    __syncthreads();                           // E
    if (tid < 64)
        out[(size_t)b * 64 + tid] =
            scr[tid] + scr[64 + tid] + scr[128 + tid] + scr[192 + tid];
}

extern "C" void kernel_launch(void* const* d_in, const int* in_sizes, int n_in,
                              void* d_out, int out_size) {
    const float* query = (const float*)d_in[0];
    const float* keys  = (const float*)d_in[1];
    const int*   klen  = (const int*)  d_in[2];
    const float* W1    = (const float*)d_in[3];
    const float* b1    = (const float*)d_in[4];
    const float* W2    = (const float*)d_in[5];
    const float* b2    = (const float*)d_in[6];
    const float* W3    = (const float*)d_in[7];
    const float* b3    = (const float*)d_in[8];
    float* out = (float*)d_out;

    const int B = in_sizes[0] / 64;

    cudaFuncSetAttribute(asp_kernel,
                         cudaFuncAttributeMaxDynamicSharedMemorySize,
                         SMEM_TOTAL);

    asp_kernel<<<B, NTHREADS, SMEM_TOTAL>>>(query, keys, klen,
                                            W1, b1, W2, b2, W3, b3, out);
}

// round 17
// speedup vs baseline: 1.5170x; 1.0244x over previous
#include <cuda_runtime.h>
#include <cuda_fp16.h>
#include <stdint.h>
#include <math.h>
#include <float.h>

#define NTHREADS   256
#define T_REAL     200
#define MASK_VAL_F (-4294967296.0f)   // jnp.float32(-2**32+1) rounds to -2^32

// fp16 SMEM tiles, row stride 72 elements (144 B: 16B-aligned, conflict-free ldmatrix)
#define ROWB       144
#define WSTRIP     (16 * ROWB)             // 2304 B per 16-row block strip
#define NSTRIPS    13                      // ceil(200/16)

// ---- SMEM byte offsets ----
#define OFF_K     0                        // keys fp16, 13 block strips : 29952
#define OFF_WQ    (NSTRIPS * WSTRIP)       // Weff^T fp16 [64][72] : 9216 (also 512-float scratch)
#define OFF_W2    (OFF_WQ + 9216)          // W2^T  fp16 [32][72]  : 4608
#define OFF_SC    (OFF_W2 + 4608)          // fp32 scalars
#define SMEM_TOTAL (OFF_SC + 1920)         // 45696 B -> 4 CTAs/SM

// ---------------- PTX helpers (baseline, no sm_103a-only features) ----------------
static __device__ __forceinline__ uint32_t smem_u32(const void* p) {
    uint32_t a;
    asm("{ .reg .u64 t; cvta.to.shared.u64 t, %1; cvt.u32.u64 %0, t; }" : "=r"(a) : "l"(p));
    return a;
}

#define LDMX4(r, addr) \
    asm volatile("ldmatrix.sync.aligned.m8n8.x4.shared.b16 {%0,%1,%2,%3}, [%4];" \
        : "=r"((r)[0]), "=r"((r)[1]), "=r"((r)[2]), "=r"((r)[3]) : "r"(addr))

#define MMA16816(d, a0, a1, a2, a3, b0, b1) \
    asm volatile("mma.sync.aligned.m16n8k16.row.col.f32.f16.f16.f32 " \
        "{%0,%1,%2,%3},{%4,%5,%6,%7},{%8,%9},{%0,%1,%2,%3};" \
        : "+f"((d)[0]), "+f"((d)[1]), "+f"((d)[2]), "+f"((d)[3]) \
        : "r"(a0), "r"(a1), "r"(a2), "r"(a3), "r"(b0), "r"(b1))

// pack (x0 -> low half, x1 -> high half) into one fp16x2 register
static __device__ __forceinline__ uint32_t h2pack(float x0, float x1) {
    uint32_t h;
    asm("cvt.rn.f16x2.f32 %0, %1, %2;" : "=r"(h) : "f"(x1), "f"(x0));
    return h;
}

__device__ __forceinline__ float warpRedMax(float v) {
    #pragma unroll
    for (int o = 16; o > 0; o >>= 1) v = fmaxf(v, __shfl_xor_sync(0xffffffffu, v, o));
    return v;
}
__device__ __forceinline__ float warpRedSum(float v) {
    #pragma unroll
    for (int o = 16; o > 0; o >>= 1) v += __shfl_xor_sync(0xffffffffu, v, o);
    return v;
}

extern "C" __global__ void __launch_bounds__(NTHREADS, 4)
asp_kernel(const float* __restrict__ query,
           const float* __restrict__ keys,
           const int*   __restrict__ klw,
           const float* __restrict__ W1,
           const float* __restrict__ b1,
           const float* __restrict__ W2,
           const float* __restrict__ b2,
           const float* __restrict__ W3,
           const float* __restrict__ b3,
           float* __restrict__ out)
{
    extern __shared__ char sbase[];
    const uint32_t sb = smem_u32(sbase);

    float* qWbS = (float*)(sbase + OFF_SC);          // 64
    float* b2S  = qWbS + 64;                         // 32
    float* W3S  = b2S  + 32;                         // 32
    float* wS   = W3S  + 32;                         // 256 (also qWb-partial scratch)

    const int b    = blockIdx.x;
    const int tid  = threadIdx.x;
    const int lane = tid & 31;
    const int warp = tid >> 5;

    const float* qg = query + (size_t)b * 64;
    const float* kg = keys  + (size_t)b * T_REAL * 64;

    int len;
    {
        const bool is64 = ((klw[1] | klw[3] | klw[5] | klw[7] | klw[9] | klw[11]) == 0);
        len = is64 ? klw[2 * b] : klw[b];
    }
    if (len > T_REAL) len = T_REAL;
    const int nblk = (len + 15) >> 4;          // blocks needing GEMM
    const int lenW  = (len == 0) ? T_REAL : len;
    const int nblkS = (lenW + 15) >> 4;        // strips needing staging
    const float b3v = b3[0];

    // ---- small operands (no barrier; consumed only after later syncs) ----
    if (tid < 32)       W3S[tid]    = W3[tid];
    else if (tid < 64)  b2S[tid-32] = b2[tid-32];

    // ---- keys staging FIRST: DRAM latency overlaps the weight transform ----
    #pragma unroll 1
    for (int bi = 0; bi < 2; bi++) {
        const int blk = warp + bi * 8;
        if (blk >= nblkS) continue;
        char* stp = sbase + OFF_K + blk * WSTRIP;
        #pragma unroll
        for (int it = 0; it < 8; it++) {
            const int idx = it * 32 + lane;
            const int row = idx >> 4, q4 = idx & 15;
            const int t = blk * 16 + row;
            float4 v = make_float4(0.f, 0.f, 0.f, 0.f);
            if (t < T_REAL) v = ((const float4*)kg)[t * 16 + q4];
            *(uint2*)(stp + row*ROWB + q4*8) =
                make_uint2(h2pack(v.x, v.y), h2pack(v.z, v.w));
        }
    }

    // ---- Weff^T fp16, vectorized over j-pairs (float2 LDGs) ----
    // WqT[j][i] = W1b[i][j] - W1c[i][j] + q_i * W1d[i][j]
    for (int idx = tid; idx < 1024; idx += NTHREADS) {
        const int j  = (idx & 31) * 2;
        const int i0 = (idx >> 5) * 2;
        const float2 pb0 = *(const float2*)&W1[(64 +i0)*64 + j];
        const float2 pb1 = *(const float2*)&W1[(65 +i0)*64 + j];
        const float2 pc0 = *(const float2*)&W1[(128+i0)*64 + j];
        const float2 pc1 = *(const float2*)&W1[(129+i0)*64 + j];
        const float2 pd0 = *(const float2*)&W1[(192+i0)*64 + j];
        const float2 pd1 = *(const float2*)&W1[(193+i0)*64 + j];
        const float q0 = __ldg(qg + i0), q1 = __ldg(qg + i0 + 1);
        *(uint32_t*)(sbase + OFF_WQ + j*ROWB + i0*2) =
            h2pack(pb0.x - pc0.x + q0*pd0.x, pb1.x - pc1.x + q1*pd1.x);
        *(uint32_t*)(sbase + OFF_WQ + (j+1)*ROWB + i0*2) =
            h2pack(pb0.y - pc0.y + q0*pd0.y, pb1.y - pc1.y + q1*pd1.y);
    }
    // ---- W2^T fp16 ----
    for (int idx = tid; idx < 1024; idx += NTHREADS) {
        const int n = idx & 31, i0 = (idx >> 5) * 2;
        *(uint32_t*)(sbase + OFF_W2 + n*ROWB + i0*2) =
            h2pack(W2[i0*32 + n], W2[(i0+1)*32 + n]);
    }
    // ---- qWb partials: thread (g=tid>>6, j=tid&63) sums i in [16g,16g+16) ----
    {
        const int j = tid & 63, g = tid >> 6;
        float s = 0.f;
        #pragma unroll 4
        for (int i = 16 * g; i < 16 * g + 16; i++)
            s += __ldg(qg + i) * (W1[i*64 + j] + W1[(128+i)*64 + j]);
        wS[tid] = s;
    }
    __syncthreads();                           // A: transform + partials done
    if (tid < 64)
        qWbS[tid] = b1[tid] + wS[tid] + wS[64+tid] + wS[128+tid] + wS[192+tid];
    __syncthreads();                           // B: qWbS ready; wS free

    // ---- ldmatrix lane addressing ----
    const uint32_t laneR16 = lane & 15;
    const uint32_t laneC   = (lane >> 4) << 3;
    const uint32_t bNt = (lane >> 4) & 1;
    const uint32_t bK  = ((lane >> 3) & 1) << 3;
    const uint32_t bR  = lane & 7;
    const uint32_t bBase = (uint32_t)(bNt * 8 + bR) * ROWB + bK * 2;

    // ================= per-warp independent 16-row blocks =================
    #pragma unroll 1
    for (int bi = 0; bi < 2; bi++) {
        const int blk = warp + bi * 8;
        if (blk >= nblk) continue;
        const uint32_t myK = sb + OFF_K + blk * WSTRIP;

        // ---- layer 1: C1[16 x 64] ----
        float c1[8][4];
        #pragma unroll
        for (int q = 0; q < 8; q++)
            #pragma unroll
            for (int x = 0; x < 4; x++) c1[q][x] = 0.f;

        #pragma unroll
        for (int kk = 0; kk < 4; kk++) {
            const uint32_t aoff = laneR16 * ROWB + (kk*16 + laneC) * 2;
            uint32_t aH[4];
            LDMX4(aH, myK + aoff);
            #pragma unroll
            for (int pp = 0; pp < 4; pp++) {           // nt pairs
                const uint32_t boff = (uint32_t)(pp * 16) * ROWB + kk * 32 + bBase;
                uint32_t bH[4];
                LDMX4(bH, sb + OFF_WQ + boff);
                MMA16816(c1[pp*2+0], aH[0], aH[1], aH[2], aH[3], bH[0], bH[1]);
                MMA16816(c1[pp*2+1], aH[0], aH[1], aH[2], aH[3], bH[2], bH[3]);
            }
        }

        // ---- epilogue 1: h1 = relu(C1 + qWb) -> fp16 -> layer-2 A frags ----
        uint32_t a2[4][4];
        #pragma unroll
        for (int nt = 0; nt < 8; nt++) {
            const int n0 = nt*8 + 2*(lane & 3);
            const float x0 = fmaxf(c1[nt][0] + qWbS[n0],   0.f);
            const float x1 = fmaxf(c1[nt][1] + qWbS[n0+1], 0.f);
            const float x2 = fmaxf(c1[nt][2] + qWbS[n0],   0.f);
            const float x3 = fmaxf(c1[nt][3] + qWbS[n0+1], 0.f);
            const int kk2 = nt >> 1, s = (nt & 1) * 2;
            a2[kk2][s+0] = h2pack(x0, x1);
            a2[kk2][s+1] = h2pack(x2, x3);
        }

        // ---- layer 2: C2[16 x 32] ----
        float c2[4][4];
        #pragma unroll
        for (int q = 0; q < 4; q++)
            #pragma unroll
            for (int x = 0; x < 4; x++) c2[q][x] = 0.f;

        #pragma unroll
        for (int kk = 0; kk < 4; kk++) {
            #pragma unroll
            for (int pp = 0; pp < 2; pp++) {           // nt pairs (N=32)
                const uint32_t boff = (uint32_t)(pp * 16) * ROWB + kk * 32 + bBase;
                uint32_t bH[4];
                LDMX4(bH, sb + OFF_W2 + boff);
                MMA16816(c2[pp*2+0], a2[kk][0], a2[kk][1], a2[kk][2], a2[kk][3], bH[0], bH[1]);
                MMA16816(c2[pp*2+1], a2[kk][0], a2[kk][1], a2[kk][2], a2[kk][3], bH[2], bH[3]);
            }
        }

        // ---- epilogue 2: score = relu(C2 + b2) . W3 (quad reduce) ----
        float p0 = 0.f, p1 = 0.f;
        #pragma unroll
        for (int nt = 0; nt < 4; nt++) {
            const int n0 = nt*8 + 2*(lane & 3);
            const float w0 = W3S[n0], w1 = W3S[n0+1];
            const float bb0 = b2S[n0], bb1 = b2S[n0+1];
            p0 += fmaxf(c2[nt][0] + bb0, 0.f) * w0 + fmaxf(c2[nt][1] + bb1, 0.f) * w1;
            p1 += fmaxf(c2[nt][2] + bb0, 0.f) * w0 + fmaxf(c2[nt][3] + bb1, 0.f) * w1;
        }
        p0 += __shfl_xor_sync(0xffffffffu, p0, 1);
        p0 += __shfl_xor_sync(0xffffffffu, p0, 2);
        p1 += __shfl_xor_sync(0xffffffffu, p1, 1);
        p1 += __shfl_xor_sync(0xffffffffu, p1, 2);
        if ((lane & 3) == 0) {
            wS[blk*16 + (lane >> 2)]     = p0 + b3v;
            wS[blk*16 + (lane >> 2) + 8] = p1 + b3v;
        }
    }
    __syncthreads();                           // C: scores ready

    // ---- single-warp softmax (warp 0 holds all 256 slots in regs) ----
    if (warp == 0) {
        float v[8];
        float mx = -FLT_MAX;
        #pragma unroll
        for (int i = 0; i < 8; i++) {
            const int t = lane + 32 * i;
            float s;
            if (t < T_REAL) s = (t < len) ? wS[t] : MASK_VAL_F;
            else            s = -FLT_MAX;
            v[i] = s;
            mx = fmaxf(mx, s);
        }
        mx = warpRedMax(mx);
        float sum = 0.f;
        #pragma unroll
        for (int i = 0; i < 8; i++) {
            const int t = lane + 32 * i;
            const float e = (t < T_REAL) ? __expf(v[i] - mx) : 0.f;
            v[i] = e;
            sum += e;
        }
        sum = warpRedSum(sum);
        const float inv = 1.0f / sum;
        #pragma unroll
        for (int i = 0; i < 8; i++)
            wS[lane + 32 * i] = v[i] * inv;
    }
    __syncthreads();                           // D: weights ready

    // ---- weighted sum, half2-vectorized: 32 e-pairs x 8 t-groups ----
    float* scr = (float*)(sbase + OFF_WQ);     // 512-float scratch
    {
        const int e2 = lane;                   // element pair (2*e2, 2*e2+1)
        const int g  = warp;                   // 8 t-groups
        const char* kbase = sbase + OFF_K + e2 * 4;
        float ax0 = 0.f, ay0 = 0.f, ax1 = 0.f, ay1 = 0.f;
        int t = g;
        for (; t + 8 < lenW; t += 16) {
            const float2 k0 = __half22float2(*(const __half2*)(kbase + t * ROWB));
            const float2 k1 = __half22float2(*(const __half2*)(kbase + (t + 8) * ROWB));
            const float w0 = wS[t], w1 = wS[t + 8];
            ax0 += w0 * k0.x; ay0 += w0 * k0.y;
            ax1 += w1 * k1.x; ay1 += w1 * k1.y;
        }
        if (t < lenW) {
            const float2 k0 = __half22float2(*(const __half2*)(kbase + t * ROWB));
            const float w0 = wS[t];
            ax0 += w0 * k0.x; ay0 += w0 * k0.y;
        }
        float2 acc; acc.x = ax0 + ax1; acc.y = ay0 + ay1;
        *(float2*)&scr[g * 64 + e2 * 2] = acc;
    }
    __syncthreads();                           // E
    if (tid < 64) {
        float s = 0.f;
        #pragma unroll
        for (int g = 0; g < 8; g++) s += scr[g * 64 + tid];
        out[(size_t)b * 64 + tid] = s;
    }
}

extern "C" void kernel_launch(void* const* d_in, const int* in_sizes, int n_in,
                              void* d_out, int out_size) {
    const float* query = (const float*)d_in[0];
    const float* keys  = (const float*)d_in[1];
    const int*   klen  = (const int*)  d_in[2];
    const float* W1    = (const float*)d_in[3];
    const float* b1    = (const float*)d_in[4];
    const float* W2    = (const float*)d_in[5];
    const float* b2    = (const float*)d_in[6];
    const float* W3    = (const float*)d_in[7];
    const float* b3    = (const float*)d_in[8];
    float* out = (float*)d_out;

    const int B = in_sizes[0] / 64;

    cudaFuncSetAttribute(asp_kernel,
                         cudaFuncAttributeMaxDynamicSharedMemorySize,
                         SMEM_TOTAL);

    asp_kernel<<<B, NTHREADS, SMEM_TOTAL>>>(query, keys, klen,
                                            W1, b1, W2, b2, W3, b3, out);
}